// round 6
// baseline (speedup 1.0000x reference)
#include <cuda_runtime.h>
#include <cuda_bf16.h>
#include <cstdint>

// ---------------------------------------------------------------------------
// RNN_MultiRegional_SAC — persistent bf16 mma.sync kernel, W resident in SMEM.
// h = relu(0.9 h + 0.1 (h @ W^T + drive)), 512 steps, B=32, 3H=3072.
// W_rec: 5 nonzero 1024x1024 blocks, bf16: [W00=-fixed, W02, W10, W21, W22]
//   n 0..1023:    W00 (k: h[0:1024])    + W02 (k: h[2048:3072])
//   n 1024..2047: W10 (k: h[0:1024])
//   n 2048..3071: W21 (k: h[1024:2048]) + W22 (k: h[2048:3072])
// 80 blocks, perfectly balanced (16 K128 tiles each per step):
//   bid 0..31:  str n-tile 32 (2048 K)     bid 32..63: m1 n-tile 32 (2048 K)
//   bid 64..79: thal 2 n-tiles of 32 (1024 K each)
// One grid barrier per step. fp32 master h; bf16 mma operands.
// Output (float32): [mean 32*512][std 32*512][hn_last 32*3072][rnn 32*512*3072]
// ---------------------------------------------------------------------------

#define Hh   1024
#define H3   3072
#define Bz   32
#define Tz   512
#define NEXC 717
#define HH   (Hh*Hh)
#define NBLK 80
#define SMEM_W  131072                    // 16 tiles x 8192 B
#define SMEM_H  24576                     // 3 tiles x 8192 B
#define SMEM_TOTAL (SMEM_W + SMEM_H)

__device__ __align__(256) __nv_bfloat16 g_Wb[5u * HH];      // 10 MB
__device__ __align__(256) float         g_hf[2][Bz * H3];   // fp32 master h [b][n]
__device__ __align__(256) __nv_bfloat16 g_hb[2][Bz * H3];   // bf16 operand h [b][n]
__device__ unsigned g_cnt;                                   // barrier counter
__device__ unsigned g_gen;                                   // barrier generation

// ---------------- helpers ----------------
__device__ __forceinline__ void cp16(unsigned dst, const void* src) {
    asm volatile("cp.async.cg.shared.global [%0], [%1], 16;" :: "r"(dst), "l"(src));
}
#define CP_COMMIT() asm volatile("cp.async.commit_group;")
#define CP_WAIT1()  asm volatile("cp.async.wait_group 1;")
#define CP_WAIT0()  asm volatile("cp.async.wait_group 0;")

__device__ __forceinline__ unsigned smem_u32(const void* p) {
    return (unsigned)__cvta_generic_to_shared(p);
}

// ---------------- prep: build packed bf16 W blocks -----------------------------
__global__ void prep_kernel(const float* __restrict__ w_str2thal,
                            const float* __restrict__ w_m12m1,
                            const float* __restrict__ w_m12str,
                            const float* __restrict__ w_thal2m1,
                            const float* __restrict__ fixedw) {
    int idx = blockIdx.x * blockDim.x + threadIdx.x;
    if (idx >= HH) return;
    int c = idx & (Hh - 1);
    g_Wb[0u * HH + idx] = __float2bfloat16(-fixedw[idx]);
    float v = fminf(fmaxf(w_m12str[idx], 1e-10f), 1.0f);
    g_Wb[1u * HH + idx] = __float2bfloat16((c < NEXC) ? v : 0.0f);
    v = fminf(fmaxf(w_str2thal[idx], 1e-10f), 1.0f);
    g_Wb[2u * HH + idx] = __float2bfloat16((c < (Hh / 2)) ? v : -v);
    g_Wb[3u * HH + idx] = __float2bfloat16(fminf(fmaxf(w_thal2m1[idx], 1e-10f), 1.0f));
    v = fminf(fmaxf(w_m12m1[idx], 1e-10f), 1.0f);
    g_Wb[4u * HH + idx] = __float2bfloat16((c < NEXC) ? v : -v);
}

// ---------------- init: hn ([1][32][3072] = [b][n]) -> h masters ---------------
__global__ void init_kernel(const float* __restrict__ hn) {
    int idx = blockIdx.x * blockDim.x + threadIdx.x;
    if (idx >= Bz * H3) return;
    float v = hn[idx];
    g_hf[0][idx] = v;
    g_hb[0][idx] = __float2bfloat16(v);
}

// ---------------- persistent tensor-core kernel --------------------------------
__global__ void __launch_bounds__(256, 1) rnn_persist(const float* __restrict__ inp,
                                                      const float* __restrict__ iw,
                                                      float* __restrict__ rnn) {
    extern __shared__ __align__(256) unsigned char smem[];
    unsigned char* sW = smem;               // 16 x 8192: [tile][n=32][k=128] swizzled
    unsigned char* sH = smem + SMEM_W;      // 3 x 8192 rotating h tiles

    const int tx   = threadIdx.x;
    const int bid  = blockIdx.x;
    const int wid  = tx >> 5;
    const int lane = tx & 31;
    const bool isThal = (bid >= 64);

    // ---- region descriptors ----
    int n0, nloc;
    const __nv_bfloat16 *wsrc0, *wsrc1;
    int wrow0, wrow1, hseg0, hseg1;
    if (bid < 32)      { n0 = bid * 32;              nloc = n0;
                         wsrc0 = g_Wb;               wsrc1 = g_Wb + 1u*HH;
                         wrow0 = nloc; wrow1 = nloc; hseg0 = 0;    hseg1 = 2048; }
    else if (bid < 64) { n0 = 2048 + (bid - 32)*32;  nloc = n0 & (Hh-1);
                         wsrc0 = g_Wb + 3u*HH;       wsrc1 = g_Wb + 4u*HH;
                         wrow0 = nloc; wrow1 = nloc; hseg0 = 1024; hseg1 = 2048; }
    else               { n0 = 1024 + (bid - 64)*64;  nloc = (bid - 64)*64;
                         wsrc0 = g_Wb + 2u*HH;       wsrc1 = g_Wb + 2u*HH;
                         wrow0 = nloc; wrow1 = nloc + 32; hseg0 = 0; hseg1 = 0; }

    const unsigned sWaddr = smem_u32(sW);
    const unsigned sHaddr = smem_u32(sH);

    // ---- prologue: load all 16 W tiles into smem (once) ----
#pragma unroll 1
    for (int kt = 0; kt < 16; kt++) {
        const __nv_bfloat16* wp = (kt < 8 ? wsrc0 : wsrc1)
                                + (size_t)(kt < 8 ? wrow0 : wrow1) * Hh + ((kt & 7) << 7);
#pragma unroll
        for (int i = 0; i < 2; i++) {
            int c = tx + i * 256;           // chunk 0..511
            int r = c >> 4, col = c & 15;
            cp16(sWaddr + kt * 8192 + r * 256 + ((col ^ (r & 7)) << 4),
                 wp + (size_t)r * Hh + col * 8);
        }
    }
    CP_COMMIT();
    CP_WAIT0();
    __syncthreads();

    // ---- ldmatrix lane addressing ----
    const int bt = wid & 1, nh = wid >> 1;
    const int am = lane >> 3;
    const int arow = bt * 16 + (am & 1) * 8 + (lane & 7);   // A row (batch)
    const int qa   = am >> 1;
    const int sa   = arow & 7;
    const int brow = nh * 8 + (lane & 7);                   // B row (n)
    const int grp  = lane >> 3;
    const int sb   = brow & 7;
    const unsigned habase = sHaddr + arow * 256;
    const unsigned wbbase = sWaddr + brow * 256;

    // ---- epilogue constants (hoisted out of time loop) ----
    const int g  = lane >> 2, tg = lane & 3;
    const int ncol0 = n0 + nh * 8 + 2 * tg;
    const int nsets = isThal ? 2 : 1;
    float iwv[2][2][4];
#pragma unroll
    for (int s = 0; s < 2; s++)
        if (s < nsets)
#pragma unroll
            for (int j = 0; j < 2; j++)
#pragma unroll
                for (int i = 0; i < 4; i++)
                    iwv[s][j][i] = iw[i * H3 + ncol0 + s * 32 + j];

    unsigned tgt;
    asm volatile("ld.volatile.global.u32 %0, [%1];" : "=r"(tgt) : "l"(&g_gen));

    // =================== time loop ===================
#pragma unroll 1
    for (int t = 0; t < Tz; t++) {
        const int cur = t & 1, nxt = cur ^ 1;
        const __nv_bfloat16* __restrict__ hbcur = g_hb[cur];

        // h tile staging lambda (tile kt -> buffer kt%3)
        auto stage_h = [&](int kt) {
            const __nv_bfloat16* hp = hbcur + (kt < 8 ? hseg0 : hseg1) + ((kt & 7) << 7);
            unsigned hB = sHaddr + (kt % 3) * 8192;
#pragma unroll
            for (int i = 0; i < 2; i++) {
                int c = tx + i * 256;
                int r = c >> 4, col = c & 15;
                cp16(hB + r * 256 + ((col ^ (r & 7)) << 4), hp + (size_t)r * H3 + col * 8);
            }
            CP_COMMIT();
        };

        stage_h(0);
        stage_h(1);

        float d[2][2][4];
#pragma unroll
        for (int s = 0; s < 2; s++)
#pragma unroll
            for (int e = 0; e < 2; e++)
#pragma unroll
                for (int j = 0; j < 4; j++) d[s][e][j] = 0.f;

#pragma unroll 1
        for (int kt = 0; kt < 16; kt++) {
            CP_WAIT1();
            __syncthreads();
            if (kt + 2 < 16) stage_h(kt + 2);
            else CP_COMMIT();

            const unsigned ha = habase + (kt % 3) * 8192;
            const unsigned wa = wbbase + kt * 8192;
            const int sel = (isThal && kt >= 8) ? 1 : 0;

#pragma unroll
            for (int kp = 0; kp < 4; kp++) {
                unsigned b0, b1, b2, b3;
                asm volatile("ldmatrix.sync.aligned.m8n8.x4.shared.b16 {%0,%1,%2,%3}, [%4];"
                             : "=r"(b0), "=r"(b1), "=r"(b2), "=r"(b3)
                             : "r"(wa + (((4 * kp + grp) ^ sb) << 4)));
                unsigned a0, a1, a2, a3;
                asm volatile("ldmatrix.sync.aligned.m8n8.x4.shared.b16 {%0,%1,%2,%3}, [%4];"
                             : "=r"(a0), "=r"(a1), "=r"(a2), "=r"(a3)
                             : "r"(ha + (((4 * kp + qa) ^ sa) << 4)));
                asm volatile("mma.sync.aligned.m16n8k16.row.col.f32.bf16.bf16.f32 "
                             "{%0,%1,%2,%3}, {%4,%5,%6,%7}, {%8,%9}, {%0,%1,%2,%3};"
                             : "+f"(d[sel][0][0]), "+f"(d[sel][0][1]), "+f"(d[sel][0][2]), "+f"(d[sel][0][3])
                             : "r"(a0), "r"(a1), "r"(a2), "r"(a3), "r"(b0), "r"(b1));
                unsigned c0, c1, c2, c3;
                asm volatile("ldmatrix.sync.aligned.m8n8.x4.shared.b16 {%0,%1,%2,%3}, [%4];"
                             : "=r"(c0), "=r"(c1), "=r"(c2), "=r"(c3)
                             : "r"(ha + (((4 * kp + 2 + qa) ^ sa) << 4)));
                asm volatile("mma.sync.aligned.m16n8k16.row.col.f32.bf16.bf16.f32 "
                             "{%0,%1,%2,%3}, {%4,%5,%6,%7}, {%8,%9}, {%0,%1,%2,%3};"
                             : "+f"(d[sel][1][0]), "+f"(d[sel][1][1]), "+f"(d[sel][1][2]), "+f"(d[sel][1][3])
                             : "r"(c0), "r"(c1), "r"(c2), "r"(c3), "r"(b2), "r"(b3));
            }
        }

        // ---- epilogue: drive + relu update; write h masters + rnn ----
        {
            float* __restrict__ hfn = g_hf[nxt];
            __nv_bfloat16* __restrict__ hbn = g_hb[nxt];
            const float* __restrict__ hfc = g_hf[cur];
#pragma unroll
            for (int s = 0; s < 2; s++) {
                if (s >= nsets) break;
                const int ncol = ncol0 + s * 32;
                float ds[4];
#pragma unroll
                for (int j = 0; j < 4; j++) ds[j] = d[s][0][j] + d[s][1][j];
#pragma unroll
                for (int half = 0; half < 2; half++) {
                    int b = bt * 16 + g + half * 8;
                    float4 iv = ((const float4*)inp)[b * Tz + t];
#pragma unroll
                    for (int j = 0; j < 2; j++) {
                        int n = ncol + j;
                        float sum = ds[half * 2 + j];
                        float drv = iv.x * iwv[s][j][0] + iv.y * iwv[s][j][1]
                                  + iv.z * iwv[s][j][2] + iv.w * iwv[s][j][3];
                        float hp = hfc[b * H3 + n];
                        float v = fmaxf(0.9f * hp + 0.1f * (sum + drv), 0.0f);
                        hfn[b * H3 + n] = v;
                        hbn[b * H3 + n] = __float2bfloat16(v);
                        rnn[((size_t)(b * Tz + t)) * H3 + n] = v;
                    }
                }
            }
        }

        // ---- grid barrier ----
        __syncthreads();
        if (tx == 0) {
            __threadfence();
            ++tgt;
            if (atomicAdd(&g_cnt, 1u) == NBLK - 1) {
                g_cnt = 0;
                __threadfence();
                atomicExch(&g_gen, tgt);
            } else {
                unsigned curgen;
                do {
                    __nanosleep(32);
                    asm volatile("ld.volatile.global.u32 %0, [%1];" : "=r"(curgen) : "l"(&g_gen));
                } while ((int)(curgen - tgt) < 0);
                __threadfence();
            }
        } else { ++tgt; }
        __syncthreads();
    }
}

// ---------------- heads: mean/std over masked (m1) region ----------------------
__global__ void head_kernel(const float* __restrict__ rnn,
                            const float* __restrict__ mean_w, const float* __restrict__ mean_b,
                            const float* __restrict__ std_w,  const float* __restrict__ std_b,
                            float* __restrict__ mean_out, float* __restrict__ std_out) {
    int warp = blockIdx.x * 8 + (threadIdx.x >> 5);   // = b*512 + t
    int lane = threadIdx.x & 31;
    const float* row = rnn + (size_t)warp * H3 + 2048;
    float sm = 0.0f, ss = 0.0f;
#pragma unroll 8
    for (int i = lane; i < Hh; i += 32) {
        float v = row[i];
        sm += v * mean_w[2048 + i];
        ss += v * std_w[2048 + i];
    }
#pragma unroll
    for (int off = 16; off; off >>= 1) {
        sm += __shfl_down_sync(0xFFFFFFFFu, sm, off);
        ss += __shfl_down_sync(0xFFFFFFFFu, ss, off);
    }
    if (lane == 0) {
        mean_out[warp] = sm + mean_b[0];
        float s = ss + std_b[0];
        std_out[warp] = fminf(fmaxf(s, -5.0f), 10.0f);
    }
}

// ---------------- hn_last copy --------------------------------------------------
__global__ void hn_kernel(const float* __restrict__ rnn, float* __restrict__ hn_out) {
    int idx = blockIdx.x * blockDim.x + threadIdx.x;
    if (idx >= Bz * H3) return;
    int b = idx / H3, n = idx - b * H3;
    hn_out[idx] = rnn[((size_t)(b * Tz + (Tz - 1))) * H3 + n];
}

// ---------------- launch ---------------------------------------------------------
extern "C" void kernel_launch(void* const* d_in, const int* in_sizes, int n_in,
                              void* d_out, int out_size) {
    const float* inp        = (const float*)d_in[0];   // [32,512,4]
    const float* hn         = (const float*)d_in[1];   // [1,32,3072]
    // d_in[2] = w_str2str (unused: its mask is all-zeros in the reference)
    const float* w_str2thal = (const float*)d_in[3];
    const float* w_m12m1    = (const float*)d_in[4];
    const float* w_m12str   = (const float*)d_in[5];
    const float* w_thal2m1  = (const float*)d_in[6];
    const float* fixedw     = (const float*)d_in[7];
    const float* inp_weight = (const float*)d_in[8];   // [4,3072]
    const float* mean_w     = (const float*)d_in[9];   // [1,3072]
    const float* mean_b     = (const float*)d_in[10];  // [1]
    const float* std_w      = (const float*)d_in[11];
    const float* std_b      = (const float*)d_in[12];
    // d_in[13] = sampling flag

    float* out      = (float*)d_out;
    float* mean_out = out;                         // 32*512
    float* std_out  = out + 16384;                 // 32*512
    float* hn_out   = out + 32768;                 // 32*3072
    float* rnn      = out + 131072;                // 32*512*3072

    cudaFuncSetAttribute(rnn_persist, cudaFuncAttributeMaxDynamicSharedMemorySize, SMEM_TOTAL);

    prep_kernel<<<(HH + 255) / 256, 256>>>(w_str2thal, w_m12m1, w_m12str, w_thal2m1, fixedw);
    init_kernel<<<(Bz * H3 + 255) / 256, 256>>>(hn);

    rnn_persist<<<NBLK, 256, SMEM_TOTAL>>>(inp, inp_weight, rnn);

    head_kernel<<<2048, 256>>>(rnn, mean_w, mean_b, std_w, std_b, mean_out, std_out);
    hn_kernel<<<(Bz * H3 + 255) / 256, 256>>>(rnn, hn_out);
}

// round 7
// speedup vs baseline: 1.1831x; 1.1831x over previous
#include <cuda_runtime.h>
#include <cuda_bf16.h>
#include <cstdint>

// ---------------------------------------------------------------------------
// RNN_MultiRegional_SAC — bf16 mma.sync, K-split pairs + second-arriver combine.
// h = relu(0.9 h + 0.1 (h @ W^T + drive)), 512 steps, B=32, 3H=3072.
// W_rec: 5 nonzero 1024x1024 blocks bf16: [W00=-fixed, W02, W10, W21, W22]
//   n 0..1023:    W00 (k: h[0:1024])    + W02 (k: h[2048:3072])
//   n 1024..2047: W10 (k: h[0:1024])
//   n 2048..3071: W21 (k: h[1024:2048]) + W22 (k: h[2048:3072])
// Grid 160 blocks/step, each exactly 8 K128-tiles over a 32-n strip:
//   bid 0..63:   str  pair=bid>>1, khalf=bid&1 (W00 | W02)
//   bid 64..127: m1   pair=32+((bid-64)>>1)    (W21 | W22)
//   bid 128..159: thal (W10), no pairing
// Paired halves: both write 4KB partials, fence, atomicAdd per-(t,pair) flag;
// second arriver adds partner partial and runs the epilogue. No spinning.
// Output (float32): [mean 32*512][std 32*512][hn_last 32*3072][rnn 32*512*3072]
// ---------------------------------------------------------------------------

#define Hh   1024
#define H3   3072
#define Bz   32
#define Tz   512
#define NEXC 717
#define HH   (Hh*Hh)

__device__ __align__(256) __nv_bfloat16 g_Wb[5u * HH];      // 10 MB
__device__ __align__(256) float         g_hf[2][Bz * H3];   // fp32 master h [b][n]
__device__ __align__(256) __nv_bfloat16 g_hb[2][Bz * H3];   // bf16 operand h [b][n]
__device__ __align__(256) float         g_part[64 * 2 * 1024]; // [pair][khalf][n32*b32]
__device__ int g_flag[Tz * 64];                              // per-(step,pair) arrive count

// ---------------- helpers ----------------
__device__ __forceinline__ void cp16(unsigned dst, const void* src) {
    asm volatile("cp.async.cg.shared.global [%0], [%1], 16;" :: "r"(dst), "l"(src));
}
#define CP_COMMIT() asm volatile("cp.async.commit_group;")
#define CP_WAIT1()  asm volatile("cp.async.wait_group 1;")

__device__ __forceinline__ unsigned smem_u32(const void* p) {
    return (unsigned)__cvta_generic_to_shared(p);
}

// ---------------- prep: build packed bf16 W blocks + zero flags ----------------
__global__ void prep_kernel(const float* __restrict__ w_str2thal,
                            const float* __restrict__ w_m12m1,
                            const float* __restrict__ w_m12str,
                            const float* __restrict__ w_thal2m1,
                            const float* __restrict__ fixedw) {
    int idx = blockIdx.x * blockDim.x + threadIdx.x;
    if (idx >= HH) return;
    if (idx < Tz * 64) g_flag[idx] = 0;
    int c = idx & (Hh - 1);
    g_Wb[0u * HH + idx] = __float2bfloat16(-fixedw[idx]);
    float v = fminf(fmaxf(w_m12str[idx], 1e-10f), 1.0f);
    g_Wb[1u * HH + idx] = __float2bfloat16((c < NEXC) ? v : 0.0f);
    v = fminf(fmaxf(w_str2thal[idx], 1e-10f), 1.0f);
    g_Wb[2u * HH + idx] = __float2bfloat16((c < (Hh / 2)) ? v : -v);
    g_Wb[3u * HH + idx] = __float2bfloat16(fminf(fmaxf(w_thal2m1[idx], 1e-10f), 1.0f));
    v = fminf(fmaxf(w_m12m1[idx], 1e-10f), 1.0f);
    g_Wb[4u * HH + idx] = __float2bfloat16((c < NEXC) ? v : -v);
}

// ---------------- init: hn ([1][32][3072] = [b][n]) -> h masters ---------------
__global__ void init_kernel(const float* __restrict__ hn) {
    int idx = blockIdx.x * blockDim.x + threadIdx.x;
    if (idx >= Bz * H3) return;
    float v = hn[idx];
    g_hf[0][idx] = v;
    g_hb[0][idx] = __float2bfloat16(v);
}

// ---------------- per-step tensor-core kernel ----------------------------------
// 256 threads = 8 warps; warp = (bt = w&1: batch half, nh = w>>1: n-octet).
// Each warp: full 1024-K (8 tiles) for a 16b x 8n fragment. K-tile 128,
// 3-stage cp.async pipeline, XOR-swizzled smem (chunk16 ^= row&7).
__global__ void __launch_bounds__(256, 2) step_mma(int t,
                                                   const float* __restrict__ inp,
                                                   const float* __restrict__ iw,
                                                   float* __restrict__ rnn) {
    __shared__ __align__(256) unsigned char sWb[3][8192];   // [n=32][k=128] bf16
    __shared__ __align__(256) unsigned char sHb[3][8192];   // [b=32][k=128] bf16
    __shared__ int swin;

    const int tx   = threadIdx.x;
    const int bid  = blockIdx.x;
    const int wid  = tx >> 5;
    const int lane = tx & 31;
    const int cur  = t & 1, nxt = cur ^ 1;

    // ---- block decode ----
    int n0, pair, khalf, hseg;
    const __nv_bfloat16* wsrc;
    bool thal = false;
    if (bid < 64)       { int ntl = bid >> 1;        khalf = bid & 1; n0 = ntl * 32;        pair = ntl;
                          wsrc = khalf ? g_Wb + 1u*HH : g_Wb;          hseg = khalf ? 2048 : 0; }
    else if (bid < 128) { int ntl = (bid - 64) >> 1; khalf = bid & 1; n0 = 2048 + ntl * 32; pair = 32 + ntl;
                          wsrc = khalf ? g_Wb + 4u*HH : g_Wb + 3u*HH;  hseg = khalf ? 2048 : 1024; }
    else                { int ntl = bid - 128;       khalf = 0;       n0 = 1024 + ntl * 32; pair = 0;
                          wsrc = g_Wb + 2u*HH;                         hseg = 0; thal = true; }
    const int nloc = n0 & (Hh - 1);

    const __nv_bfloat16* __restrict__ hbcur = g_hb[cur];
    const unsigned sWaddr = smem_u32(sWb);
    const unsigned sHaddr = smem_u32(sHb);

    // ---- staging (W tile + H tile, 4 cp16/thread) ----
    auto stage = [&](int kt, int bf) {
        const __nv_bfloat16* wp = wsrc + (size_t)nloc * Hh + (kt << 7);
        const __nv_bfloat16* hp = hbcur + hseg + (kt << 7);
        unsigned wB = sWaddr + bf * 8192;
        unsigned hB = sHaddr + bf * 8192;
#pragma unroll
        for (int i = 0; i < 2; i++) {
            int c = tx + i * 256;               // chunk 0..511
            int r = c >> 4, col = c & 15;
            unsigned off = r * 256 + ((col ^ (r & 7)) << 4);
            cp16(wB + off, wp + (size_t)r * Hh + col * 8);
            cp16(hB + off, hp + (size_t)r * H3 + col * 8);
        }
        CP_COMMIT();
    };

    // ---- ldmatrix lane addressing ----
    const int bt = wid & 1, nh = wid >> 1;
    const int am = lane >> 3;
    const int arow = bt * 16 + (am & 1) * 8 + (lane & 7);   // A row (batch)
    const int qa   = am >> 1;
    const int sa   = arow & 7;
    const int brow = nh * 8 + (lane & 7);                   // B row (n)
    const int grp  = lane >> 3;
    const int sb   = brow & 7;
    const unsigned habase = sHaddr + arow * 256;
    const unsigned wbbase = sWaddr + brow * 256;

    stage(0, 0);
    stage(1, 1);

    float d[2][4];
#pragma unroll
    for (int e = 0; e < 2; e++)
#pragma unroll
        for (int j = 0; j < 4; j++) d[e][j] = 0.f;

#pragma unroll 1
    for (int kt = 0; kt < 8; kt++) {
        CP_WAIT1();
        __syncthreads();
        if (kt + 2 < 8) stage(kt + 2, (kt + 2) % 3);
        else CP_COMMIT();

        const unsigned ha = habase + (kt % 3) * 8192;
        const unsigned wa = wbbase + (kt % 3) * 8192;
#pragma unroll
        for (int kp = 0; kp < 4; kp++) {
            unsigned b0, b1, b2, b3;
            asm volatile("ldmatrix.sync.aligned.m8n8.x4.shared.b16 {%0,%1,%2,%3}, [%4];"
                         : "=r"(b0), "=r"(b1), "=r"(b2), "=r"(b3)
                         : "r"(wa + (((4 * kp + grp) ^ sb) << 4)));
            unsigned a0, a1, a2, a3;
            asm volatile("ldmatrix.sync.aligned.m8n8.x4.shared.b16 {%0,%1,%2,%3}, [%4];"
                         : "=r"(a0), "=r"(a1), "=r"(a2), "=r"(a3)
                         : "r"(ha + (((4 * kp + qa) ^ sa) << 4)));
            asm volatile("mma.sync.aligned.m16n8k16.row.col.f32.bf16.bf16.f32 "
                         "{%0,%1,%2,%3}, {%4,%5,%6,%7}, {%8,%9}, {%0,%1,%2,%3};"
                         : "+f"(d[0][0]), "+f"(d[0][1]), "+f"(d[0][2]), "+f"(d[0][3])
                         : "r"(a0), "r"(a1), "r"(a2), "r"(a3), "r"(b0), "r"(b1));
            unsigned c0, c1, c2, c3;
            asm volatile("ldmatrix.sync.aligned.m8n8.x4.shared.b16 {%0,%1,%2,%3}, [%4];"
                         : "=r"(c0), "=r"(c1), "=r"(c2), "=r"(c3)
                         : "r"(ha + (((4 * kp + 2 + qa) ^ sa) << 4)));
            asm volatile("mma.sync.aligned.m16n8k16.row.col.f32.bf16.bf16.f32 "
                         "{%0,%1,%2,%3}, {%4,%5,%6,%7}, {%8,%9}, {%0,%1,%2,%3};"
                         : "+f"(d[1][0]), "+f"(d[1][1]), "+f"(d[1][2]), "+f"(d[1][3])
                         : "r"(c0), "r"(c1), "r"(c2), "r"(c3), "r"(b2), "r"(b3));
        }
    }

    float ds[4];
#pragma unroll
    for (int j = 0; j < 4; j++) ds[j] = d[0][j] + d[1][j];

    // output fragment coords: value ds[half*2+j] -> (b = bt*16 + half*8 + g, n = ncol0 + j)
    const int g  = lane >> 2, tg = lane & 3;
    const int pn = nh * 8 + 2 * tg;          // local n (for partials)
    const int pb = bt * 16 + g;              // local b (half adds 8)

    // ---- pair combine: write partials, second arriver proceeds ----
    if (!thal) {
        float* pp = g_part + (pair * 2 + khalf) * 1024;
#pragma unroll
        for (int half = 0; half < 2; half++)
#pragma unroll
            for (int j = 0; j < 2; j++)
                pp[(pn + j) * 32 + pb + half * 8] = ds[half * 2 + j];
        __threadfence();
        __syncthreads();
        if (tx == 0) swin = atomicAdd(&g_flag[t * 64 + pair], 1);
        __syncthreads();
        if (swin == 0) return;               // first arriver: partner will finish
        __threadfence();                     // acquire
        const float* qq = g_part + (pair * 2 + (khalf ^ 1)) * 1024;
#pragma unroll
        for (int half = 0; half < 2; half++)
#pragma unroll
            for (int j = 0; j < 2; j++)
                ds[half * 2 + j] += __ldcg(&qq[(pn + j) * 32 + pb + half * 8]);
    }

    // ---- epilogue: drive + relu update; write h masters + rnn ----
    {
        const int ncol = n0 + pn;
        float* __restrict__ hfn = g_hf[nxt];
        __nv_bfloat16* __restrict__ hbn = g_hb[nxt];
        const float* __restrict__ hfc = g_hf[cur];

        float iwv[2][4];
#pragma unroll
        for (int j = 0; j < 2; j++)
#pragma unroll
            for (int i = 0; i < 4; i++) iwv[j][i] = iw[i * H3 + ncol + j];

#pragma unroll
        for (int half = 0; half < 2; half++) {
            int b = pb + half * 8;
            float4 iv = ((const float4*)inp)[b * Tz + t];
#pragma unroll
            for (int j = 0; j < 2; j++) {
                int n = ncol + j;
                float drv = iv.x * iwv[j][0] + iv.y * iwv[j][1]
                          + iv.z * iwv[j][2] + iv.w * iwv[j][3];
                float hp = hfc[b * H3 + n];
                float v = fmaxf(0.9f * hp + 0.1f * (ds[half * 2 + j] + drv), 0.0f);
                hfn[b * H3 + n] = v;
                hbn[b * H3 + n] = __float2bfloat16(v);
                rnn[((size_t)(b * Tz + t)) * H3 + n] = v;
            }
        }
    }
}

// ---------------- heads: mean/std over masked (m1) region ----------------------
__global__ void head_kernel(const float* __restrict__ rnn,
                            const float* __restrict__ mean_w, const float* __restrict__ mean_b,
                            const float* __restrict__ std_w,  const float* __restrict__ std_b,
                            float* __restrict__ mean_out, float* __restrict__ std_out) {
    int warp = blockIdx.x * 8 + (threadIdx.x >> 5);   // = b*512 + t
    int lane = threadIdx.x & 31;
    const float* row = rnn + (size_t)warp * H3 + 2048;
    float sm = 0.0f, ss = 0.0f;
#pragma unroll 8
    for (int i = lane; i < Hh; i += 32) {
        float v = row[i];
        sm += v * mean_w[2048 + i];
        ss += v * std_w[2048 + i];
    }
#pragma unroll
    for (int off = 16; off; off >>= 1) {
        sm += __shfl_down_sync(0xFFFFFFFFu, sm, off);
        ss += __shfl_down_sync(0xFFFFFFFFu, ss, off);
    }
    if (lane == 0) {
        mean_out[warp] = sm + mean_b[0];
        float s = ss + std_b[0];
        std_out[warp] = fminf(fmaxf(s, -5.0f), 10.0f);
    }
}

// ---------------- hn_last copy --------------------------------------------------
__global__ void hn_kernel(const float* __restrict__ rnn, float* __restrict__ hn_out) {
    int idx = blockIdx.x * blockDim.x + threadIdx.x;
    if (idx >= Bz * H3) return;
    int b = idx / H3, n = idx - b * H3;
    hn_out[idx] = rnn[((size_t)(b * Tz + (Tz - 1))) * H3 + n];
}

// ---------------- launch ---------------------------------------------------------
extern "C" void kernel_launch(void* const* d_in, const int* in_sizes, int n_in,
                              void* d_out, int out_size) {
    const float* inp        = (const float*)d_in[0];   // [32,512,4]
    const float* hn         = (const float*)d_in[1];   // [1,32,3072]
    // d_in[2] = w_str2str (unused: its mask is all-zeros in the reference)
    const float* w_str2thal = (const float*)d_in[3];
    const float* w_m12m1    = (const float*)d_in[4];
    const float* w_m12str   = (const float*)d_in[5];
    const float* w_thal2m1  = (const float*)d_in[6];
    const float* fixedw     = (const float*)d_in[7];
    const float* inp_weight = (const float*)d_in[8];   // [4,3072]
    const float* mean_w     = (const float*)d_in[9];   // [1,3072]
    const float* mean_b     = (const float*)d_in[10];  // [1]
    const float* std_w      = (const float*)d_in[11];
    const float* std_b      = (const float*)d_in[12];
    // d_in[13] = sampling flag

    float* out      = (float*)d_out;
    float* mean_out = out;                         // 32*512
    float* std_out  = out + 16384;                 // 32*512
    float* hn_out   = out + 32768;                 // 32*3072
    float* rnn      = out + 131072;                // 32*512*3072

    prep_kernel<<<(HH + 255) / 256, 256>>>(w_str2thal, w_m12m1, w_m12str, w_thal2m1, fixedw);
    init_kernel<<<(Bz * H3 + 255) / 256, 256>>>(hn);

    for (int t = 0; t < Tz; t++)
        step_mma<<<160, 256>>>(t, inp, inp_weight, rnn);

    head_kernel<<<2048, 256>>>(rnn, mean_w, mean_b, std_w, std_b, mean_out, std_out);
    hn_kernel<<<(Bz * H3 + 255) / 256, 256>>>(rnn, hn_out);
}